// round 7
// baseline (speedup 1.0000x reference)
#include <cuda_runtime.h>
#include <cstdint>

#define HH   480
#define WW   640
#define DIMC 32
#define NB   8
#define HWSZ (HH * WW)
#define NPIX (NB * HWSZ)   // 2,457,600 sites

// Scratch in [site, DIM] layout. Zero-initialized at module load; finalize
// restores zeros to every line it dirties, so "scratch == 0 on entry" holds
// on every call (graph-replay deterministic). Lines never hit stay clean.
__device__ float g_sum[(size_t)NPIX * DIMC];   // ~314.6 MB
__device__ float g_cnt[NPIX];                  // ~9.8 MB
__device__ int   g_off[NB];                    // canonical int32 offsets

// Normalize offsets to int32 whether harness stored int64 or int32.
// int64 LE: words = [v0, 0, v1, 0, ...]; int32: [v0, v1, ...] with v1 != 0.
__global__ void prep_offsets_kernel(const int* __restrict__ o32)
{
    bool is64 = (o32[1] == 0);
#pragma unroll
    for (int i = 0; i < NB; i++)
        g_off[i] = is64 ? o32[2 * i] : o32[i];
}

// 8 threads per event; each does one float4 vector-RED (channels part*4..+3).
__global__ void scatter_kernel(const float* __restrict__ events,
                               const float* __restrict__ features,
                               int n)
{
    int t = blockIdx.x * blockDim.x + threadIdx.x;
    int e = t >> 3;
    if (e >= n) return;
    int part = t & 7;

    float2 ev = __ldg((const float2*)events + e);   // broadcast within 8-lane group

    // jnp.round == round-half-even == __float2int_rn; then clip
    int x = __float2int_rn(ev.x * (float)WW);
    int y = __float2int_rn(ev.y * (float)HH);
    x = min(max(x, 0), WW - 1);
    y = min(max(y, 0), HH - 1);

    // searchsorted(offsets, e, side='right') = count of offsets <= e
    int b = 0;
#pragma unroll
    for (int i = 0; i < NB; i++)
        b += (e >= g_off[i]) ? 1 : 0;

    int pix = (b * HH + y) * WW + x;

    float4 f = __ldg((const float4*)features + (size_t)e * 8 + part);

    float* dst = g_sum + (size_t)pix * DIMC + part * 4;
    asm volatile("red.global.add.v4.f32 [%0], {%1, %2, %3, %4};"
                 :: "l"(dst), "f"(f.x), "f"(f.y), "f"(f.z), "f"(f.w)
                 : "memory");
    if (part == 0) {
        asm volatile("red.global.add.f32 [%0], %1;"
                     :: "l"(g_cnt + pix), "f"(1.0f)
                     : "memory");
    }
}

// One block per 32 consecutive sites. Phase 1: warp 0 reads counts, builds a
// hit mask, restores cnt zeros (only where dirty). Phase 2: threads read
// g_sum ONLY for hit sites (128B-aligned lines -> skipped sites cause zero
// DRAM traffic) and restore zeros there. Phase 3: smem transpose, normalize,
// coalesced float4 write to out[B,D,H,W].
__global__ void finalize_kernel(float* __restrict__ out)
{
    __shared__ float s[32][33];
    __shared__ float sinv[32];
    __shared__ unsigned int hitmask;

    int tid  = threadIdx.x;            // 0..255
    int pix0 = blockIdx.x * 32;

    if (tid < 32) {
        float c = g_cnt[pix0 + tid];
        sinv[tid] = 1.0f / fmaxf(c, 1.0f);
        unsigned m = __ballot_sync(0xffffffffu, c != 0.0f);
        if (tid == 0) hitmask = m;
        if (c != 0.0f) g_cnt[pix0 + tid] = 0.0f;   // restore invariant
    }
    __syncthreads();

    int p  = tid >> 3;
    int c0 = (tid & 7) * 4;
    float4 v = make_float4(0.f, 0.f, 0.f, 0.f);
    if (hitmask & (1u << p)) {
        float4* gsp = (float4*)g_sum + (size_t)pix0 * 8 + tid;
        v = *gsp;
        *gsp = make_float4(0.f, 0.f, 0.f, 0.f);   // restore invariant
    }
    s[p][c0 + 0] = v.x;
    s[p][c0 + 1] = v.y;
    s[p][c0 + 2] = v.z;
    s[p][c0 + 3] = v.w;
    __syncthreads();

    int d   = tid >> 3;
    int px0 = (tid & 7) * 4;
    float4 o;
    o.x = s[px0 + 0][d] * sinv[px0 + 0];
    o.y = s[px0 + 1][d] * sinv[px0 + 1];
    o.z = s[px0 + 2][d] * sinv[px0 + 2];
    o.w = s[px0 + 3][d] * sinv[px0 + 3];

    // pix0 multiple of 32; W=640 and H*W multiples of 32 -> tile never
    // crosses a row or batch boundary.
    int bb  = pix0 / HWSZ;
    int rem = pix0 - bb * HWSZ;
    float4* orow = (float4*)(out + (size_t)bb * DIMC * HWSZ + (size_t)d * HWSZ + rem);
    orow[tid & 7] = o;
}

extern "C" void kernel_launch(void* const* d_in, const int* in_sizes, int n_in,
                              void* d_out, int out_size)
{
    const float* events   = (const float*)d_in[0];
    const float* features = (const float*)d_in[1];
    const int*   offs_raw = (const int*)d_in[2];
    int n = in_sizes[0] / 2;

    prep_offsets_kernel<<<1, 1>>>(offs_raw);

    const int threads = 256;
    int total  = n * 8;                         // 8 threads per event
    int blocks = (total + threads - 1) / threads;
    scatter_kernel<<<blocks, threads>>>(events, features, n);

    finalize_kernel<<<NPIX / 32, 256>>>((float*)d_out);
}

// round 8
// speedup vs baseline: 3.7161x; 3.7161x over previous
#include <cuda_runtime.h>
#include <cstdint>

#define HH   480
#define WW   640
#define DIMC 32
#define NB   8
#define HWSZ (HH * WW)
#define NPIX (NB * HWSZ)   // 2,457,600 sites

// Scratch in [site, DIM] layout: one event touches one contiguous 128B line.
__device__ float g_sum[(size_t)NPIX * DIMC];   // ~314.6 MB
__device__ float g_cnt[NPIX];                  // ~9.8 MB
__device__ int   g_off[NB];                    // canonical int32 offsets

// Normalize offsets to int32 whether harness stored int64 or int32.
// int64 LE: words = [v0, 0, v1, 0, ...]; int32: [v0, v1, ...] with v1 != 0.
__global__ void prep_offsets_kernel(const int* __restrict__ o32)
{
    bool is64 = (o32[1] == 0);
#pragma unroll
    for (int i = 0; i < NB; i++)
        g_off[i] = is64 ? o32[2 * i] : o32[i];
}

// 8 threads per event; each does one float4 vector-RED (channels part*4..+3).
__global__ void scatter_kernel(const float* __restrict__ events,
                               const float* __restrict__ features,
                               int n)
{
    int t = blockIdx.x * blockDim.x + threadIdx.x;
    int e = t >> 3;
    if (e >= n) return;
    int part = t & 7;

    float2 ev = __ldg((const float2*)events + e);   // broadcast within 8-lane group

    // jnp.round == round-half-even == __float2int_rn; then clip
    int x = __float2int_rn(ev.x * (float)WW);
    int y = __float2int_rn(ev.y * (float)HH);
    x = min(max(x, 0), WW - 1);
    y = min(max(y, 0), HH - 1);

    // searchsorted(offsets, e, side='right') = count of offsets <= e
    int b = 0;
#pragma unroll
    for (int i = 0; i < NB; i++)
        b += (e >= g_off[i]) ? 1 : 0;

    int pix = (b * HH + y) * WW + x;

    float4 f = __ldg((const float4*)features + (size_t)e * 8 + part);

    float* dst = g_sum + (size_t)pix * DIMC + part * 4;
    asm volatile("red.global.add.v4.f32 [%0], {%1, %2, %3, %4};"
                 :: "l"(dst), "f"(f.x), "f"(f.y), "f"(f.z), "f"(f.w)
                 : "memory");
    if (part == 0) {
        asm volatile("red.global.add.f32 [%0], %1;"
                     :: "l"(g_cnt + pix), "f"(1.0f)
                     : "memory");
    }
}

// One block per 32 consecutive sites: read counts first, load g_sum only for
// hit sites (site == exact 128B line -> skipped sites cost zero DRAM sectors),
// normalize, transpose via smem, write [B, D, H, W] coalesced as float4.
// Zeros for empty sites come from the memset (no restore stores).
__global__ void finalize_kernel(float* __restrict__ out)
{
    __shared__ float s[32][33];
    __shared__ float sinv[32];
    __shared__ unsigned int hitmask;

    int tid  = threadIdx.x;            // 0..255
    int pix0 = blockIdx.x * 32;

    if (tid < 32) {
        float c = g_cnt[pix0 + tid];
        sinv[tid] = 1.0f / fmaxf(c, 1.0f);
        unsigned m = __ballot_sync(0xffffffffu, c != 0.0f);
        if (tid == 0) hitmask = m;
    }
    __syncthreads();

    int p  = tid >> 3;
    int c0 = (tid & 7) * 4;
    float4 v = make_float4(0.f, 0.f, 0.f, 0.f);
    if (hitmask & (1u << p))
        v = __ldg((const float4*)g_sum + (size_t)pix0 * 8 + tid);
    s[p][c0 + 0] = v.x;
    s[p][c0 + 1] = v.y;
    s[p][c0 + 2] = v.z;
    s[p][c0 + 3] = v.w;
    __syncthreads();

    int d   = tid >> 3;
    int px0 = (tid & 7) * 4;
    float4 o;
    o.x = s[px0 + 0][d] * sinv[px0 + 0];
    o.y = s[px0 + 1][d] * sinv[px0 + 1];
    o.z = s[px0 + 2][d] * sinv[px0 + 2];
    o.w = s[px0 + 3][d] * sinv[px0 + 3];

    // pix0 multiple of 32; W and H*W multiples of 32 -> tile never crosses
    // a row or batch boundary.
    int bb  = pix0 / HWSZ;
    int rem = pix0 - bb * HWSZ;
    float4* orow = (float4*)(out + (size_t)bb * DIMC * HWSZ + (size_t)d * HWSZ + rem);
    orow[tid & 7] = o;
}

extern "C" void kernel_launch(void* const* d_in, const int* in_sizes, int n_in,
                              void* d_out, int out_size)
{
    const float* events   = (const float*)d_in[0];
    const float* features = (const float*)d_in[1];
    const int*   offs_raw = (const int*)d_in[2];
    int n = in_sizes[0] / 2;

    void* sum_ptr = nullptr;
    void* cnt_ptr = nullptr;
    cudaGetSymbolAddress(&sum_ptr, g_sum);
    cudaGetSymbolAddress(&cnt_ptr, g_cnt);
    cudaMemsetAsync(sum_ptr, 0, (size_t)NPIX * DIMC * sizeof(float), 0);
    cudaMemsetAsync(cnt_ptr, 0, (size_t)NPIX * sizeof(float), 0);

    prep_offsets_kernel<<<1, 1>>>(offs_raw);

    const int threads = 256;
    int total  = n * 8;                         // 8 threads per event
    int blocks = (total + threads - 1) / threads;
    scatter_kernel<<<blocks, threads>>>(events, features, n);

    finalize_kernel<<<NPIX / 32, 256>>>((float*)d_out);
}